// round 1
// baseline (speedup 1.0000x reference)
#include <cuda_runtime.h>
#include <math.h>

#define DT 0.1f
#define EPS 1e-6f
#define PI_F 3.14159265358979323846f
#define TWO_PI_F 6.28318530717958647692f

constexpr int BA = 128;   // agents per block (1 thread computes 1 agent)

__global__ __launch_bounds__(BA)
void ekf_kernel(const float* __restrict__ x,
                const float* __restrict__ P,
                const float* __restrict__ a,
                const float* __restrict__ Y,
                const float* __restrict__ n1,
                const float* __restrict__ n2s,
                const float* __restrict__ n2k,
                const float* __restrict__ gains,
                const float* __restrict__ og,
                float* __restrict__ out,
                int N)
{
    __shared__ float sP9[BA * 9];
    __shared__ float sx [BA * 5];
    __shared__ float sa [BA * 2];
    __shared__ float oX [BA * 5];
    __shared__ float oP [BA * 25];
    __shared__ float oK [BA * 10];

    const int tid  = threadIdx.x;
    const int base = blockIdx.x * BA;
    const int nv   = min(BA, N - base);
    if (nv <= 0) return;

    // ---- coalesced input staging ----
    for (int t = tid; t < nv * 5; t += BA) sx[t] = x[(size_t)base * 5 + t];
    for (int t = tid; t < nv * 2; t += BA) sa[t] = a[(size_t)base * 2 + t];
    for (int t = tid; t < nv * 25; t += BA) {
        int e = t % 25, i = e / 5, j = e % 5;
        if (i < 3 && j < 3) {
            int n = t / 25;
            sP9[n * 9 + i * 3 + j] = P[(size_t)base * 25 + t];
        }
    }
    __syncthreads();

    if (tid < nv) {
        const int g = base + tid;
        // broadcast scalars (same address per warp -> 1 transaction)
        const float q0 = expf(2.f * n1[0]);
        const float q1 = expf(2.f * n1[1]);
        const float q2 = expf(2.f * n1[2]);
        const float q3 = expf(2.f * n1[3]);
        const float q4 = expf(2.f * n1[4]);
        const float es0 = expf(2.f * n2s[0]);
        const float es1 = expf(2.f * n2s[1]);
        const float ek0 = expf(2.f * n2k[0]);
        const float ek1 = expf(2.f * n2k[1]);
        const float g0 = gains[0], g1 = gains[1];
        const float og0 = og[0],   og1 = og[1];

        const float vel = g0 * sa[tid * 2 + 0];
        const float w   = g1 * sa[tid * 2 + 1];

        // range_angle(x2 + w*dt): jnp.mod has sign of divisor (positive)
        float r = fmodf(sx[tid * 5 + 2] + w * DT + PI_F, TWO_PI_F);
        if (r < 0.f) r += TWO_PI_F;
        const float ang = r - PI_F;

        float s, c;
        sincosf(ang, &s, &c);
        const float px = fminf(fmaxf(sx[tid * 5 + 0] + vel * c * DT, -1.f), 1.f);
        const float py = fminf(fmaxf(sx[tid * 5 + 1] + vel * s * DT, -1.f), 1.f);

        // A[0,2], A[1,2]
        const float a0 = -vel * s * DT;
        const float a1 =  vel * c * DT;

        const float p00 = sP9[tid * 9 + 0], p01 = sP9[tid * 9 + 1], p02 = sP9[tid * 9 + 2];
        const float p10 = sP9[tid * 9 + 3], p11 = sP9[tid * 9 + 4], p12 = sP9[tid * 9 + 5];
        const float p20 = sP9[tid * 9 + 6], p21 = sP9[tid * 9 + 7], p22 = sP9[tid * 9 + 8];

        // T = B*P with B = [[1,0,a0],[0,1,a1],[0,0,1]]
        const float t00 = p00 + a0 * p20, t01 = p01 + a0 * p21, t02 = p02 + a0 * p22;
        const float t10 = p10 + a1 * p20, t11 = p11 + a1 * p21, t12 = p12 + a1 * p22;
        // M = T*Bᵀ
        const float m00 = t00 + a0 * t02, m01 = t01 + a1 * t02, m02 = t02;
        const float m10 = t10 + a0 * t12, m11 = t11 + a1 * t12, m12 = t12;
        const float m20 = p20 + a0 * p22, m21 = p21 + a1 * p22, m22 = p22;

        // symmetrized 3x3 block + Q diag + EPS
        const float P00 = m00 + q0 + EPS;
        const float P11 = m11 + q1 + EPS;
        const float P22 = m22 + q2 + EPS;
        const float P01 = 0.5f * (m01 + m10);
        const float P02 = 0.5f * (m02 + m20);
        const float P12 = 0.5f * (m12 + m21);

        // diagonal S and the only two nonzero K entries
        const float sa_ = og0 * og0 * q3 + vel * vel * ek0 + es0;
        const float sd_ = og1 * og1 * q4 + w   * w   * ek1 + es1;
        const float K30 = q3 * og0 / sa_;
        const float K41 = q4 * og1 / sd_;
        const float P33 = (1.f - K30 * og0) * q3 + EPS;
        const float P44 = (1.f - K41 * og1) * q4 + EPS;

        const float Y0 = Y[g];
        const float Y1 = Y[(size_t)N + g];
        const float x3 = vel + K30 * (Y0 - og0 * vel);
        const float x4 = w   + K41 * (Y1 - og1 * w);

        oX[tid * 5 + 0] = px;
        oX[tid * 5 + 1] = py;
        oX[tid * 5 + 2] = ang;
        oX[tid * 5 + 3] = x3;
        oX[tid * 5 + 4] = x4;

        float* op = &oP[tid * 25];
        #pragma unroll
        for (int k = 0; k < 25; k++) op[k] = 0.f;
        op[0]  = P00; op[1]  = P01; op[2]  = P02;
        op[5]  = P01; op[6]  = P11; op[7]  = P12;
        op[10] = P02; op[11] = P12; op[12] = P22;
        op[18] = P33; op[24] = P44;

        float* ok = &oK[tid * 10];
        #pragma unroll
        for (int k = 0; k < 10; k++) ok[k] = 0.f;
        ok[6] = K30;   // K[3,0]
        ok[9] = K41;   // K[4,1]
    }
    __syncthreads();

    // ---- coalesced output stores: layout = x_new[N*5] | P_new[N*25] | K[N*10] ----
    float* outX = out;
    float* outP = out + (size_t)N * 5;
    float* outK = out + (size_t)N * 30;
    for (int t = tid; t < nv * 5;  t += BA) outX[(size_t)base * 5  + t] = oX[t];
    for (int t = tid; t < nv * 25; t += BA) outP[(size_t)base * 25 + t] = oP[t];
    for (int t = tid; t < nv * 10; t += BA) outK[(size_t)base * 10 + t] = oK[t];
}

extern "C" void kernel_launch(void* const* d_in, const int* in_sizes, int n_in,
                              void* d_out, int out_size) {
    const float* x    = (const float*)d_in[0];
    const float* P    = (const float*)d_in[1];
    const float* a    = (const float*)d_in[2];
    const float* Y    = (const float*)d_in[3];
    const float* n1   = (const float*)d_in[4];
    const float* n2s  = (const float*)d_in[5];
    const float* n2k  = (const float*)d_in[6];
    const float* gns  = (const float*)d_in[7];
    const float* og   = (const float*)d_in[8];
    float* out = (float*)d_out;

    const int N = in_sizes[0] / 5;
    const int blocks = (N + BA - 1) / BA;
    ekf_kernel<<<blocks, BA>>>(x, P, a, Y, n1, n2s, n2k, gns, og, out, N);
}

// round 2
// speedup vs baseline: 1.1894x; 1.1894x over previous
#include <cuda_runtime.h>
#include <math.h>

#define DT 0.1f
#define EPS 1e-6f
#define PI_F 3.14159265358979323846f
#define TWO_PI_F 6.28318530717958647692f

constexpr int BA = 128;   // agents per block (1 thread computes 1 agent)

struct Consts {
    float q0, q1, q2, q3, q4;
    float es0, es1, ek0, ek1;
    float g0, g1, og0, og1;
};

__global__ __launch_bounds__(BA)
void ekf_kernel(const float* __restrict__ x,
                const float* __restrict__ P,
                const float* __restrict__ a,
                const float* __restrict__ Y,
                const float* __restrict__ n1,
                const float* __restrict__ n2s,
                const float* __restrict__ n2k,
                const float* __restrict__ gains,
                const float* __restrict__ og,
                float* __restrict__ out,
                int N)
{
    // sP: P input, reused for P_new output.  sx: x input, reused for x_new output.
    __shared__ __align__(16) float sP [BA * 25];
    __shared__ __align__(16) float sx [BA * 5];
    __shared__ __align__(16) float sa2[BA * 2];
    __shared__ __align__(16) float sK [BA * 10];
    __shared__ Consts C;

    const int tid  = threadIdx.x;
    const int base = blockIdx.x * BA;
    const int nv   = min(BA, N - base);
    if (nv <= 0) return;

    if (tid == 0) {
        C.q0  = expf(2.f * n1[0]);
        C.q1  = expf(2.f * n1[1]);
        C.q2  = expf(2.f * n1[2]);
        C.q3  = expf(2.f * n1[3]);
        C.q4  = expf(2.f * n1[4]);
        C.es0 = expf(2.f * n2s[0]);
        C.es1 = expf(2.f * n2s[1]);
        C.ek0 = expf(2.f * n2k[0]);
        C.ek1 = expf(2.f * n2k[1]);
        C.g0  = gains[0]; C.g1 = gains[1];
        C.og0 = og[0];    C.og1 = og[1];
    }

    // ---- coalesced, vectorized input staging ----
    if (nv == BA) {
        const float4* Pv = (const float4*)(P + (size_t)base * 25);
        const float4* xv = (const float4*)(x + (size_t)base * 5);
        const float4* av = (const float4*)(a + (size_t)base * 2);
        float4* sPv = (float4*)sP;
        float4* sxv = (float4*)sx;
        float4* sav = (float4*)sa2;
        #pragma unroll
        for (int k = 0; k < (BA * 25 / 4) / BA; k++)      // 6 full passes
            sPv[tid + k * BA] = Pv[tid + k * BA];
        if (tid < (BA * 25 / 4) - 6 * BA)                 // 32 remainder
            sPv[tid + 6 * BA] = Pv[tid + 6 * BA];
        sxv[tid + 0] = xv[tid + 0];                       // 160 = 128 + 32
        if (tid < (BA * 5 / 4) - BA) sxv[tid + BA] = xv[tid + BA];
        if (tid < BA * 2 / 4)        sav[tid] = av[tid];  // 64
    } else {
        for (int t = tid; t < nv * 25; t += BA) sP [t] = P[(size_t)base * 25 + t];
        for (int t = tid; t < nv * 5;  t += BA) sx [t] = x[(size_t)base * 5  + t];
        for (int t = tid; t < nv * 2;  t += BA) sa2[t] = a[(size_t)base * 2  + t];
    }
    __syncthreads();

    if (tid < nv) {
        const int g = base + tid;

        const float vel = C.g0 * sa2[tid * 2 + 0];
        const float w   = C.g1 * sa2[tid * 2 + 1];

        // range_angle(x2 + w*dt): jnp.mod has sign of divisor (positive)
        float r = fmodf(sx[tid * 5 + 2] + w * DT + PI_F, TWO_PI_F);
        if (r < 0.f) r += TWO_PI_F;
        const float ang = r - PI_F;

        float s, c;
        sincosf(ang, &s, &c);
        const float px = fminf(fmaxf(sx[tid * 5 + 0] + vel * c * DT, -1.f), 1.f);
        const float py = fminf(fmaxf(sx[tid * 5 + 1] + vel * s * DT, -1.f), 1.f);

        const float a0 = -vel * s * DT;   // A[0,2]
        const float a1 =  vel * c * DT;   // A[1,2]

        const float* p = &sP[tid * 25];
        const float p00 = p[0],  p01 = p[1],  p02 = p[2];
        const float p10 = p[5],  p11 = p[6],  p12 = p[7];
        const float p20 = p[10], p21 = p[11], p22 = p[12];

        // M = B*P*Bt, B = [[1,0,a0],[0,1,a1],[0,0,1]]
        const float t00 = p00 + a0 * p20, t01 = p01 + a0 * p21, t02 = p02 + a0 * p22;
        const float t10 = p10 + a1 * p20, t11 = p11 + a1 * p21, t12 = p12 + a1 * p22;
        const float m00 = t00 + a0 * t02, m01 = t01 + a1 * t02, m02 = t02;
        const float m10 = t10 + a0 * t12, m11 = t11 + a1 * t12, m12 = t12;
        const float m20 = p20 + a0 * p22, m21 = p21 + a1 * p22, m22 = p22;

        const float P00 = m00 + C.q0 + EPS;
        const float P11 = m11 + C.q1 + EPS;
        const float P22 = m22 + C.q2 + EPS;
        const float P01 = 0.5f * (m01 + m10);
        const float P02 = 0.5f * (m02 + m20);
        const float P12 = 0.5f * (m12 + m21);

        // diagonal S; K has only [3,0] and [4,1]
        const float sa_ = C.og0 * C.og0 * C.q3 + vel * vel * C.ek0 + C.es0;
        const float sd_ = C.og1 * C.og1 * C.q4 + w   * w   * C.ek1 + C.es1;
        const float K30 = C.q3 * C.og0 / sa_;
        const float K41 = C.q4 * C.og1 / sd_;
        const float P33 = (1.f - K30 * C.og0) * C.q3 + EPS;
        const float P44 = (1.f - K41 * C.og1) * C.q4 + EPS;

        const float Y0 = Y[g];
        const float Y1 = Y[(size_t)N + g];
        const float x3 = vel + K30 * (Y0 - C.og0 * vel);
        const float x4 = w   + K41 * (Y1 - C.og1 * w);

        float* ox = &sx[tid * 5];
        ox[0] = px; ox[1] = py; ox[2] = ang; ox[3] = x3; ox[4] = x4;

        float* op = &sP[tid * 25];
        #pragma unroll
        for (int k = 0; k < 25; k++) op[k] = 0.f;
        op[0]  = P00; op[1]  = P01; op[2]  = P02;
        op[5]  = P01; op[6]  = P11; op[7]  = P12;
        op[10] = P02; op[11] = P12; op[12] = P22;
        op[18] = P33; op[24] = P44;

        float* ok = &sK[tid * 10];
        #pragma unroll
        for (int k = 0; k < 10; k++) ok[k] = 0.f;
        ok[6] = K30;   // K[3,0]
        ok[9] = K41;   // K[4,1]
    }
    __syncthreads();

    // ---- coalesced, vectorized output stores: out = x_new[N*5] | P_new[N*25] | K[N*10]
    float* outX = out;
    float* outP = out + (size_t)N * 5;
    float* outK = out + (size_t)N * 30;
    if (nv == BA) {
        float4* oXv = (float4*)(outX + (size_t)base * 5);
        float4* oPv = (float4*)(outP + (size_t)base * 25);
        float4* oKv = (float4*)(outK + (size_t)base * 10);
        const float4* sxv = (const float4*)sx;
        const float4* sPv = (const float4*)sP;
        const float4* sKv = (const float4*)sK;
        #pragma unroll
        for (int k = 0; k < 6; k++)
            oPv[tid + k * BA] = sPv[tid + k * BA];
        if (tid < (BA * 25 / 4) - 6 * BA)
            oPv[tid + 6 * BA] = sPv[tid + 6 * BA];
        oXv[tid] = sxv[tid];
        if (tid < (BA * 5 / 4) - BA) oXv[tid + BA] = sxv[tid + BA];
        oKv[tid] = sKv[tid];                               // 320 = 128+128+64
        oKv[tid + BA] = sKv[tid + BA];
        if (tid < (BA * 10 / 4) - 2 * BA) oKv[tid + 2 * BA] = sKv[tid + 2 * BA];
    } else {
        for (int t = tid; t < nv * 5;  t += BA) outX[(size_t)base * 5  + t] = sx[t];
        for (int t = tid; t < nv * 25; t += BA) outP[(size_t)base * 25 + t] = sP[t];
        for (int t = tid; t < nv * 10; t += BA) outK[(size_t)base * 10 + t] = sK[t];
    }
}

extern "C" void kernel_launch(void* const* d_in, const int* in_sizes, int n_in,
                              void* d_out, int out_size) {
    const float* x    = (const float*)d_in[0];
    const float* P    = (const float*)d_in[1];
    const float* a    = (const float*)d_in[2];
    const float* Y    = (const float*)d_in[3];
    const float* n1   = (const float*)d_in[4];
    const float* n2s  = (const float*)d_in[5];
    const float* n2k  = (const float*)d_in[6];
    const float* gns  = (const float*)d_in[7];
    const float* og   = (const float*)d_in[8];
    float* out = (float*)d_out;

    const int N = in_sizes[0] / 5;
    const int blocks = (N + BA - 1) / BA;
    ekf_kernel<<<blocks, BA>>>(x, P, a, Y, n1, n2s, n2k, gns, og, out, N);
}

// round 3
// speedup vs baseline: 1.2518x; 1.0525x over previous
#include <cuda_runtime.h>
#include <math.h>

#define DT 0.1f
#define EPS 1e-6f
#define PI_F 3.14159265358979323846f
#define TWO_PI_F 6.28318530717958647692f

constexpr int BA = 128;   // agents per block (1 thread computes 1 agent)

struct Consts {
    float q0, q1, q2, q3, q4;
    float es0, es1, ek0, ek1;
    float g0, g1, og0, og1;
};

// P stage-in: float4 indices v with v%25 in this set touch only elements
// e%25 >= 13 (outside the live 3x3 block + needed cols) -> skip.
__device__ __forceinline__ bool p_f4_dead(int m25) {
    const unsigned mask = (1u<<4)|(1u<<5)|(1u<<10)|(1u<<11)|(1u<<16)|(1u<<17)|(1u<<22)|(1u<<23)|(1u<<24);
    return (mask >> m25) & 1u;
}

__global__ __launch_bounds__(BA, 12)
void ekf_kernel(const float* __restrict__ x,
                const float* __restrict__ P,
                const float* __restrict__ a,
                const float* __restrict__ Y,
                const float* __restrict__ n1,
                const float* __restrict__ n2s,
                const float* __restrict__ n2k,
                const float* __restrict__ gains,
                const float* __restrict__ og,
                float* __restrict__ out,
                int N)
{
    __shared__ __align__(16) float sP  [BA * 25];  // P in (partial), then P_new out
    __shared__ __align__(16) float sxo [BA * 5];   // x_new out
    __shared__ float sK30[BA];
    __shared__ float sK41[BA];
    __shared__ Consts C;

    const int tid  = threadIdx.x;
    const int base = blockIdx.x * BA;
    const int nv   = min(BA, N - base);
    if (nv <= 0) return;

    if (tid == 0) {
        C.q0  = expf(2.f * n1[0]);
        C.q1  = expf(2.f * n1[1]);
        C.q2  = expf(2.f * n1[2]);
        C.q3  = expf(2.f * n1[3]);
        C.q4  = expf(2.f * n1[4]);
        C.es0 = expf(2.f * n2s[0]);
        C.es1 = expf(2.f * n2s[1]);
        C.ek0 = expf(2.f * n2k[0]);
        C.ek1 = expf(2.f * n2k[1]);
        C.g0  = gains[0]; C.g1 = gains[1];
        C.og0 = og[0];    C.og1 = og[1];
    }

    // ---- P stage-in (vectorized, dead-column f4s skipped) ----
    if (nv == BA) {
        const float4* Pv = (const float4*)(P + (size_t)base * 25);
        float4* sPv = (float4*)sP;
        int m25 = tid % 25;                      // (tid + k*128) % 25 : +3 per k
        #pragma unroll
        for (int k = 0; k < 7; k++) {
            int v = tid + k * BA;
            bool in = (k < 6) || (v < BA * 25 / 4);
            if (in && !p_f4_dead(m25)) sPv[v] = Pv[v];
            m25 += 3; if (m25 >= 25) m25 -= 25;
        }
    } else {
        for (int t = tid; t < nv * 25; t += BA) sP[t] = P[(size_t)base * 25 + t];
    }
    __syncthreads();

    if (tid < nv) {
        const int g = base + tid;

        const float2 a2 = *(const float2*)(a + (size_t)g * 2);
        const float vel = C.g0 * a2.x;
        const float w   = C.g1 * a2.y;

        const float x0 = x[(size_t)g * 5 + 0];
        const float x1 = x[(size_t)g * 5 + 1];
        const float x2 = x[(size_t)g * 5 + 2];

        float r = fmodf(x2 + w * DT + PI_F, TWO_PI_F);
        if (r < 0.f) r += TWO_PI_F;
        const float ang = r - PI_F;

        float s, c;
        sincosf(ang, &s, &c);
        const float px = fminf(fmaxf(x0 + vel * c * DT, -1.f), 1.f);
        const float py = fminf(fmaxf(x1 + vel * s * DT, -1.f), 1.f);

        const float a0 = -vel * s * DT;   // A[0,2]
        const float a1 =  vel * c * DT;   // A[1,2]

        const float* p = &sP[tid * 25];
        const float p00 = p[0],  p01 = p[1],  p02 = p[2];
        const float p10 = p[5],  p11 = p[6],  p12 = p[7];
        const float p20 = p[10], p21 = p[11], p22 = p[12];

        const float t00 = p00 + a0 * p20, t01 = p01 + a0 * p21, t02 = p02 + a0 * p22;
        const float t10 = p10 + a1 * p20, t11 = p11 + a1 * p21, t12 = p12 + a1 * p22;
        const float m00 = t00 + a0 * t02, m01 = t01 + a1 * t02, m02 = t02;
        const float m10 = t10 + a0 * t12, m11 = t11 + a1 * t12, m12 = t12;
        const float m20 = p20 + a0 * p22, m21 = p21 + a1 * p22, m22 = p22;

        const float P00 = m00 + C.q0 + EPS;
        const float P11 = m11 + C.q1 + EPS;
        const float P22 = m22 + C.q2 + EPS;
        const float P01 = 0.5f * (m01 + m10);
        const float P02 = 0.5f * (m02 + m20);
        const float P12 = 0.5f * (m12 + m21);

        const float sa_ = C.og0 * C.og0 * C.q3 + vel * vel * C.ek0 + C.es0;
        const float sd_ = C.og1 * C.og1 * C.q4 + w   * w   * C.ek1 + C.es1;
        const float K30 = C.q3 * C.og0 / sa_;
        const float K41 = C.q4 * C.og1 / sd_;
        const float P33 = (1.f - K30 * C.og0) * C.q3 + EPS;
        const float P44 = (1.f - K41 * C.og1) * C.q4 + EPS;

        const float Y0 = Y[g];
        const float Y1 = Y[(size_t)N + g];
        const float x3 = vel + K30 * (Y0 - C.og0 * vel);
        const float x4 = w   + K41 * (Y1 - C.og1 * w);

        float* ox = &sxo[tid * 5];
        ox[0] = px; ox[1] = py; ox[2] = ang; ox[3] = x3; ox[4] = x4;

        float* op = &sP[tid * 25];
        op[0]  = P00; op[1]  = P01; op[2]  = P02; op[3]  = 0.f; op[4]  = 0.f;
        op[5]  = P01; op[6]  = P11; op[7]  = P12; op[8]  = 0.f; op[9]  = 0.f;
        op[10] = P02; op[11] = P12; op[12] = P22; op[13] = 0.f; op[14] = 0.f;
        op[15] = 0.f; op[16] = 0.f; op[17] = 0.f; op[18] = P33; op[19] = 0.f;
        op[20] = 0.f; op[21] = 0.f; op[22] = 0.f; op[23] = 0.f; op[24] = P44;

        sK30[tid] = K30;
        sK41[tid] = K41;
    }
    __syncthreads();

    // ---- stage-out: out = x_new[N*5] | P_new[N*25] | K[N*10] ----
    float* outX = out;
    float* outP = out + (size_t)N * 5;
    float* outK = out + (size_t)N * 30;

    if (nv == BA) {
        // P: straight float4 copy (800 f4 / block)
        float4* oPv = (float4*)(outP + (size_t)base * 25);
        const float4* sPv = (const float4*)sP;
        #pragma unroll
        for (int k = 0; k < 6; k++) oPv[tid + k * BA] = sPv[tid + k * BA];
        if (tid < BA * 25 / 4 - 6 * BA) oPv[tid + 6 * BA] = sPv[tid + 6 * BA];

        // x: straight float4 copy (160 f4)
        float4* oXv = (float4*)(outX + (size_t)base * 5);
        const float4* sxv = (const float4*)sxo;
        oXv[tid] = sxv[tid];
        if (tid < BA * 5 / 4 - BA) oXv[tid + BA] = sxv[tid + BA];

        // K: synthesized from v%5 pattern (320 f4). Elems 10a+6 = K30[a], 10a+9 = K41[a].
        float4* oKv = (float4*)(outK + (size_t)base * 10);
        int m5 = tid % 5;                 // (tid + k*128) % 5 : +3 per k
        #pragma unroll
        for (int k = 0; k < 3; k++) {
            int v = tid + k * BA;
            if (k < 2 || v < BA * 10 / 4) {
                float4 o = make_float4(0.f, 0.f, 0.f, 0.f);
                int u = v / 5;            // 20u = chunk base (2 agents per chunk)
                if (m5 == 1)      o.z = sK30[2 * u];       // elem 20u+6
                else if (m5 == 2) o.y = sK41[2 * u];       // elem 20u+9
                else if (m5 == 4) { o.x = sK30[2 * u + 1]; // elem 20u+16
                                    o.w = sK41[2 * u + 1]; } // elem 20u+19
                oKv[v] = o;
            }
            m5 += 3; if (m5 >= 5) m5 -= 5;
        }
    } else {
        for (int t = tid; t < nv * 5;  t += BA) outX[(size_t)base * 5  + t] = sxo[t];
        for (int t = tid; t < nv * 25; t += BA) outP[(size_t)base * 25 + t] = sP[t];
        for (int t = tid; t < nv * 10; t += BA) {
            int n = t / 10, e = t % 10;
            float v = 0.f;
            if (e == 6) v = sK30[n];
            else if (e == 9) v = sK41[n];
            outK[(size_t)base * 10 + t] = v;
        }
    }
}

extern "C" void kernel_launch(void* const* d_in, const int* in_sizes, int n_in,
                              void* d_out, int out_size) {
    const float* x    = (const float*)d_in[0];
    const float* P    = (const float*)d_in[1];
    const float* a    = (const float*)d_in[2];
    const float* Y    = (const float*)d_in[3];
    const float* n1   = (const float*)d_in[4];
    const float* n2s  = (const float*)d_in[5];
    const float* n2k  = (const float*)d_in[6];
    const float* gns  = (const float*)d_in[7];
    const float* og   = (const float*)d_in[8];
    float* out = (float*)d_out;

    const int N = in_sizes[0] / 5;
    const int blocks = (N + BA - 1) / BA;
    ekf_kernel<<<blocks, BA>>>(x, P, a, Y, n1, n2s, n2k, gns, og, out, N);
}

// round 4
// speedup vs baseline: 1.4216x; 1.1357x over previous
#include <cuda_runtime.h>
#include <math.h>

#define DT 0.1f
#define EPS 1e-6f
#define PI_F 3.14159265358979323846f
#define TWO_PI_F 6.28318530717958647692f

constexpr int BA = 128;   // agents per tile (1 thread = 1 agent per tile)

struct Consts {
    float q0, q1, q2, q3, q4;
    float es0, es1, ek0, ek1;
    float g0, g1, og0, og1;
};

// float4 indices v with v%25 in this set touch only dead P elements -> skip load.
__device__ __forceinline__ bool p_f4_dead(int m25) {
    const unsigned mask = (1u<<4)|(1u<<5)|(1u<<10)|(1u<<11)|(1u<<16)|(1u<<17)|(1u<<22)|(1u<<23)|(1u<<24);
    return (mask >> m25) & 1u;
}

__device__ __forceinline__ void cp16(void* dst, const void* src) {
    unsigned s = (unsigned)__cvta_generic_to_shared(dst);
    asm volatile("cp.async.cg.shared.global [%0], [%1], 16;" :: "r"(s), "l"(src) : "memory");
}
__device__ __forceinline__ void cp4(void* dst, const void* src) {
    unsigned s = (unsigned)__cvta_generic_to_shared(dst);
    asm volatile("cp.async.ca.shared.global [%0], [%1], 4;" :: "r"(s), "l"(src) : "memory");
}

__device__ __forceinline__ void prefetch_tile(const float* __restrict__ P,
                                              int base, int nv, float* dst, int tid) {
    const float4* src = (const float4*)(P + (size_t)base * 25);
    float4* d = (float4*)dst;
    const int nf4 = (nv * 25) >> 2;
    int m25 = tid % 25;
    #pragma unroll
    for (int k = 0; k < 7; k++) {
        int v = tid + k * BA;
        if (v < nf4 && !p_f4_dead(m25)) cp16(d + v, src + v);
        m25 += 3; if (m25 >= 25) m25 -= 25;
    }
    const int tail = nv * 25 - nf4 * 4;
    if (tid < tail) cp4(dst + nf4 * 4 + tid, (const float*)src + nf4 * 4 + tid);
}

__global__ __launch_bounds__(BA, 7)
void ekf_kernel(const float* __restrict__ x,
                const float* __restrict__ P,
                const float* __restrict__ a,
                const float* __restrict__ Y,
                const float* __restrict__ n1,
                const float* __restrict__ n2s,
                const float* __restrict__ n2k,
                const float* __restrict__ gains,
                const float* __restrict__ og,
                float* __restrict__ out,
                int N, int totalTiles)
{
    __shared__ __align__(16) float buf[2][BA * 25];  // P in (partial) -> P_new out, double-buffered
    __shared__ __align__(16) float sxo[BA * 5];      // x_new staging
    __shared__ float sK30[BA], sK41[BA];
    __shared__ Consts C;

    const int tid    = threadIdx.x;
    const int stride = gridDim.x;
    if (blockIdx.x >= totalTiles) return;

    if (tid == 0) {
        C.q0  = expf(2.f * n1[0]);
        C.q1  = expf(2.f * n1[1]);
        C.q2  = expf(2.f * n1[2]);
        C.q3  = expf(2.f * n1[3]);
        C.q4  = expf(2.f * n1[4]);
        C.es0 = expf(2.f * n2s[0]);
        C.es1 = expf(2.f * n2s[1]);
        C.ek0 = expf(2.f * n2k[0]);
        C.ek1 = expf(2.f * n2k[1]);
        C.g0  = gains[0]; C.g1 = gains[1];
        C.og0 = og[0];    C.og1 = og[1];
    }

    float* outX = out;
    float* outP = out + (size_t)N * 5;
    float* outK = out + (size_t)N * 30;

    // prologue: prefetch first tile into buf[0]
    {
        const int t0   = blockIdx.x;
        const int base = t0 * BA;
        prefetch_tile(P, base, min(BA, N - base), buf[0], tid);
        asm volatile("cp.async.commit_group;" ::: "memory");
    }

    int i = 0;
    for (int t = blockIdx.x; t < totalTiles; t += stride, i++) {
        const int base = t * BA;
        const int nv   = min(BA, N - base);
        float* cur = buf[i & 1];
        float* nxt = buf[(i + 1) & 1];

        // prefetch the NEXT tile in this block's sequence (overlaps with tile t work)
        const int tn = t + stride;
        if (tn < totalTiles) {
            const int bn = tn * BA;
            prefetch_tile(P, bn, min(BA, N - bn), nxt, tid);
        }
        asm volatile("cp.async.commit_group;" ::: "memory");

        // per-thread global loads for tile t (in flight during the wait)
        float x0 = 0.f, x1 = 0.f, x2 = 0.f, ain0 = 0.f, ain1 = 0.f, Y0 = 0.f, Y1 = 0.f;
        if (tid < nv) {
            const int g = base + tid;
            x0 = x[(size_t)g * 5 + 0];
            x1 = x[(size_t)g * 5 + 1];
            x2 = x[(size_t)g * 5 + 2];
            const float2 a2 = *(const float2*)(a + (size_t)g * 2);
            ain0 = a2.x; ain1 = a2.y;
            Y0 = Y[g];
            Y1 = Y[(size_t)N + g];
        }

        asm volatile("cp.async.wait_group 1;" ::: "memory");
        __syncthreads();   // tile t resident in cur, C valid

        if (tid < nv) {
            const float vel = C.g0 * ain0;
            const float w   = C.g1 * ain1;

            float r = fmodf(x2 + w * DT + PI_F, TWO_PI_F);
            if (r < 0.f) r += TWO_PI_F;
            const float ang = r - PI_F;

            float s, c;
            sincosf(ang, &s, &c);
            const float px = fminf(fmaxf(x0 + vel * c * DT, -1.f), 1.f);
            const float py = fminf(fmaxf(x1 + vel * s * DT, -1.f), 1.f);

            const float a0 = -vel * s * DT;   // A[0,2]
            const float a1 =  vel * c * DT;   // A[1,2]

            const float* p = &cur[tid * 25];
            const float p00 = p[0],  p01 = p[1],  p02 = p[2];
            const float p10 = p[5],  p11 = p[6],  p12 = p[7];
            const float p20 = p[10], p21 = p[11], p22 = p[12];

            const float t00 = p00 + a0 * p20, t01 = p01 + a0 * p21, t02 = p02 + a0 * p22;
            const float t10 = p10 + a1 * p20, t11 = p11 + a1 * p21, t12 = p12 + a1 * p22;
            const float m00 = t00 + a0 * t02, m01 = t01 + a1 * t02, m02 = t02;
            const float m10 = t10 + a0 * t12, m11 = t11 + a1 * t12, m12 = t12;
            const float m20 = p20 + a0 * p22, m21 = p21 + a1 * p22, m22 = p22;

            const float P00 = m00 + C.q0 + EPS;
            const float P11 = m11 + C.q1 + EPS;
            const float P22 = m22 + C.q2 + EPS;
            const float P01 = 0.5f * (m01 + m10);
            const float P02 = 0.5f * (m02 + m20);
            const float P12 = 0.5f * (m12 + m21);

            const float sa_ = C.og0 * C.og0 * C.q3 + vel * vel * C.ek0 + C.es0;
            const float sd_ = C.og1 * C.og1 * C.q4 + w   * w   * C.ek1 + C.es1;
            const float K30 = C.q3 * C.og0 / sa_;
            const float K41 = C.q4 * C.og1 / sd_;
            const float P33 = (1.f - K30 * C.og0) * C.q3 + EPS;
            const float P44 = (1.f - K41 * C.og1) * C.q4 + EPS;

            const float x3 = vel + K30 * (Y0 - C.og0 * vel);
            const float x4 = w   + K41 * (Y1 - C.og1 * w);

            float* ox = &sxo[tid * 5];
            ox[0] = px; ox[1] = py; ox[2] = ang; ox[3] = x3; ox[4] = x4;

            float* op = &cur[tid * 25];   // same-thread overwrite: no barrier needed
            op[0]  = P00; op[1]  = P01; op[2]  = P02; op[3]  = 0.f; op[4]  = 0.f;
            op[5]  = P01; op[6]  = P11; op[7]  = P12; op[8]  = 0.f; op[9]  = 0.f;
            op[10] = P02; op[11] = P12; op[12] = P22; op[13] = 0.f; op[14] = 0.f;
            op[15] = 0.f; op[16] = 0.f; op[17] = 0.f; op[18] = P33; op[19] = 0.f;
            op[20] = 0.f; op[21] = 0.f; op[22] = 0.f; op[23] = 0.f; op[24] = P44;

            sK30[tid] = K30;
            sK41[tid] = K41;
        }
        __syncthreads();   // outputs staged; stage-out reads cross-thread

        // ---- P_new: straight f4 copy ----
        {
            float4* o = (float4*)(outP + (size_t)base * 25);
            const float4* sv = (const float4*)cur;
            const int nf4 = (nv * 25) >> 2;
            #pragma unroll
            for (int k = 0; k < 7; k++) {
                int v = tid + k * BA;
                if (v < nf4) o[v] = sv[v];
            }
            for (int e = nf4 * 4 + tid; e < nv * 25; e += BA)
                outP[(size_t)base * 25 + e] = cur[e];
        }
        // ---- x_new ----
        {
            float4* o = (float4*)(outX + (size_t)base * 5);
            const float4* sv = (const float4*)sxo;
            const int nf4 = (nv * 5) >> 2;
            #pragma unroll
            for (int k = 0; k < 2; k++) {
                int v = tid + k * BA;
                if (v < nf4) o[v] = sv[v];
            }
            for (int e = nf4 * 4 + tid; e < nv * 5; e += BA)
                outX[(size_t)base * 5 + e] = sxo[e];
        }
        // ---- K: synthesized (elems 10n+6 = K30[n], 10n+9 = K41[n]) ----
        {
            float4* o = (float4*)(outK + (size_t)base * 10);
            const int nf4 = (nv * 10) >> 2;
            int m5 = tid % 5;
            #pragma unroll
            for (int k = 0; k < 3; k++) {
                int v = tid + k * BA;
                if (v < nf4) {
                    float4 q = make_float4(0.f, 0.f, 0.f, 0.f);
                    int u = v / 5;
                    if (m5 == 1)      q.z = sK30[2 * u];
                    else if (m5 == 2) q.y = sK41[2 * u];
                    else if (m5 == 4) { q.x = sK30[2 * u + 1]; q.w = sK41[2 * u + 1]; }
                    o[v] = q;
                }
                m5 += 3; if (m5 >= 5) m5 -= 5;
            }
            for (int e = nf4 * 4 + tid; e < nv * 10; e += BA) {
                int n = e / 10, j = e % 10;
                float vv = (j == 6) ? sK30[n] : (j == 9) ? sK41[n] : 0.f;
                outK[(size_t)base * 10 + e] = vv;
            }
        }
        // no trailing barrier: next iteration's wait+syncthreads provides the ordering
    }
}

extern "C" void kernel_launch(void* const* d_in, const int* in_sizes, int n_in,
                              void* d_out, int out_size) {
    const float* x    = (const float*)d_in[0];
    const float* P    = (const float*)d_in[1];
    const float* a    = (const float*)d_in[2];
    const float* Y    = (const float*)d_in[3];
    const float* n1   = (const float*)d_in[4];
    const float* n2s  = (const float*)d_in[5];
    const float* n2k  = (const float*)d_in[6];
    const float* gns  = (const float*)d_in[7];
    const float* og   = (const float*)d_in[8];
    float* out = (float*)d_out;

    const int N = in_sizes[0] / 5;
    const int totalTiles = (N + BA - 1) / BA;
    int blocks = 148 * 7;                 // persistent: 7 blocks/SM x 148 SMs
    if (blocks > totalTiles) blocks = totalTiles;
    ekf_kernel<<<blocks, BA>>>(x, P, a, Y, n1, n2s, n2k, gns, og, out, N, totalTiles);
}

// round 5
// speedup vs baseline: 1.7330x; 1.2190x over previous
#include <cuda_runtime.h>
#include <math.h>

#define DT 0.1f
#define EPS 1e-6f
#define PI_F 3.14159265358979323846f
#define TWO_PI_F 6.28318530717958647692f
#define INV_TWO_PI_F 0.15915494309189533577f

constexpr int BA = 128;   // agents per tile (1 thread = 1 agent per tile)

struct Consts {
    float q0, q1, q2, q3, q4;
    float es0, es1, ek0, ek1;
    float g0, g1, og0, og1;
};

// float4 indices v with v%25 in this set touch only dead P elements -> skip load.
__device__ __forceinline__ bool p_f4_dead(int m25) {
    const unsigned mask = (1u<<4)|(1u<<5)|(1u<<10)|(1u<<11)|(1u<<16)|(1u<<17)|(1u<<22)|(1u<<23)|(1u<<24);
    return (mask >> m25) & 1u;
}

__device__ __forceinline__ void cp16(void* dst, const void* src) {
    unsigned s = (unsigned)__cvta_generic_to_shared(dst);
    asm volatile("cp.async.cg.shared.global [%0], [%1], 16;" :: "r"(s), "l"(src) : "memory");
}
__device__ __forceinline__ void cp4(void* dst, const void* src) {
    unsigned s = (unsigned)__cvta_generic_to_shared(dst);
    asm volatile("cp.async.ca.shared.global [%0], [%1], 4;" :: "r"(s), "l"(src) : "memory");
}

__device__ __forceinline__ void prefetch_tile(const float* __restrict__ P,
                                              int base, int nv, float* dst, int tid) {
    const float4* src = (const float4*)(P + (size_t)base * 25);
    float4* d = (float4*)dst;
    const int nf4 = (nv * 25) >> 2;
    int m25 = tid % 25;
    #pragma unroll
    for (int k = 0; k < 7; k++) {
        int v = tid + k * BA;
        if (v < nf4 && !p_f4_dead(m25)) cp16(d + v, src + v);
        m25 += 3; if (m25 >= 25) m25 -= 25;
    }
    const int tail = nv * 25 - nf4 * 4;
    if (tid < tail) cp4(dst + nf4 * 4 + tid, (const float*)src + nf4 * 4 + tid);
}

__global__ __launch_bounds__(BA, 7)
void ekf_kernel(const float* __restrict__ x,
                const float* __restrict__ P,
                const float* __restrict__ a,
                const float* __restrict__ Y,
                const float* __restrict__ n1,
                const float* __restrict__ n2s,
                const float* __restrict__ n2k,
                const float* __restrict__ gains,
                const float* __restrict__ og,
                float* __restrict__ out,
                int N, int totalTiles)
{
    __shared__ __align__(16) float buf[2][BA * 25];  // P in (partial) -> P_new out
    __shared__ __align__(16) float sxo[BA * 5];      // x_new staging
    __shared__ float sK30[BA], sK41[BA];
    __shared__ Consts C;

    const int tid    = threadIdx.x;
    const int stride = gridDim.x;

    if (tid == 0) {
        C.q0  = expf(2.f * n1[0]);
        C.q1  = expf(2.f * n1[1]);
        C.q2  = expf(2.f * n1[2]);
        C.q3  = expf(2.f * n1[3]);
        C.q4  = expf(2.f * n1[4]);
        C.es0 = expf(2.f * n2s[0]);
        C.es1 = expf(2.f * n2s[1]);
        C.ek0 = expf(2.f * n2k[0]);
        C.ek1 = expf(2.f * n2k[1]);
        C.g0  = gains[0]; C.g1 = gains[1];
        C.og0 = og[0];    C.og1 = og[1];
    }

    float* outX = out;
    float* outP = out + (size_t)N * 5;
    float* outK = out + (size_t)N * 30;

    // ---- prologue: prefetch tile 0 (P via cp.async; scalars into registers) ----
    float x0 = 0.f, x1 = 0.f, x2 = 0.f, ain0 = 0.f, ain1 = 0.f, Y0 = 0.f, Y1 = 0.f;
    {
        const int base = blockIdx.x * BA;
        const int nv   = min(BA, N - base);
        prefetch_tile(P, base, nv, buf[0], tid);
        asm volatile("cp.async.commit_group;" ::: "memory");
        if (tid < nv) {
            const int g = base + tid;
            x0 = x[(size_t)g * 5 + 0];
            x1 = x[(size_t)g * 5 + 1];
            x2 = x[(size_t)g * 5 + 2];
            const float2 a2 = *(const float2*)(a + (size_t)g * 2);
            ain0 = a2.x; ain1 = a2.y;
            Y0 = Y[g];
            Y1 = Y[(size_t)N + g];
        }
    }

    int i = 0;
    for (int t = blockIdx.x; t < totalTiles; t += stride, i++) {
        const int base = t * BA;
        const int nv   = min(BA, N - base);
        float* cur = buf[i & 1];
        float* nxt = buf[(i + 1) & 1];

        // ---- prefetch tile t+1: P via cp.async, scalars into shadow registers ----
        const int tn = t + stride;
        float nx0 = 0.f, nx1 = 0.f, nx2 = 0.f, na0 = 0.f, na1 = 0.f, nY0 = 0.f, nY1 = 0.f;
        if (tn < totalTiles) {
            const int bn  = tn * BA;
            const int nvn = min(BA, N - bn);
            prefetch_tile(P, bn, nvn, nxt, tid);
            asm volatile("cp.async.commit_group;" ::: "memory");
            if (tid < nvn) {
                const int g = bn + tid;
                nx0 = x[(size_t)g * 5 + 0];
                nx1 = x[(size_t)g * 5 + 1];
                nx2 = x[(size_t)g * 5 + 2];
                const float2 a2 = *(const float2*)(a + (size_t)g * 2);
                na0 = a2.x; na1 = a2.y;
                nY0 = Y[g];
                nY1 = Y[(size_t)N + g];
            }
        } else {
            asm volatile("cp.async.commit_group;" ::: "memory");
        }

        asm volatile("cp.async.wait_group 1;" ::: "memory");
        __syncthreads();   // tile t resident in cur, C valid

        if (tid < nv) {
            const float vel = C.g0 * ain0;
            const float w   = C.g1 * ain1;

            // range_angle via floor-based reduction (|arg| small; matches jnp.mod)
            const float v  = x2 + w * DT;
            const float ang = fmaf(-TWO_PI_F, floorf((v + PI_F) * INV_TWO_PI_F), v);

            float s, c;
            __sincosf(ang, &s, &c);
            const float px = fminf(fmaxf(x0 + vel * c * DT, -1.f), 1.f);
            const float py = fminf(fmaxf(x1 + vel * s * DT, -1.f), 1.f);

            const float a0 = -vel * s * DT;   // A[0,2]
            const float a1 =  vel * c * DT;   // A[1,2]

            const float* p = &cur[tid * 25];
            const float p00 = p[0],  p01 = p[1],  p02 = p[2];
            const float p10 = p[5],  p11 = p[6],  p12 = p[7];
            const float p20 = p[10], p21 = p[11], p22 = p[12];

            const float t00 = p00 + a0 * p20, t01 = p01 + a0 * p21, t02 = p02 + a0 * p22;
            const float t10 = p10 + a1 * p20, t11 = p11 + a1 * p21, t12 = p12 + a1 * p22;
            const float m00 = t00 + a0 * t02, m01 = t01 + a1 * t02, m02 = t02;
            const float m10 = t10 + a0 * t12, m11 = t11 + a1 * t12, m12 = t12;
            const float m20 = p20 + a0 * p22, m21 = p21 + a1 * p22, m22 = p22;

            const float P00 = m00 + C.q0 + EPS;
            const float P11 = m11 + C.q1 + EPS;
            const float P22 = m22 + C.q2 + EPS;
            const float P01 = 0.5f * (m01 + m10);
            const float P02 = 0.5f * (m02 + m20);
            const float P12 = 0.5f * (m12 + m21);

            const float sa_ = C.og0 * C.og0 * C.q3 + vel * vel * C.ek0 + C.es0;
            const float sd_ = C.og1 * C.og1 * C.q4 + w   * w   * C.ek1 + C.es1;
            const float K30 = C.q3 * C.og0 / sa_;
            const float K41 = C.q4 * C.og1 / sd_;
            const float P33 = (1.f - K30 * C.og0) * C.q3 + EPS;
            const float P44 = (1.f - K41 * C.og1) * C.q4 + EPS;

            const float x3 = vel + K30 * (Y0 - C.og0 * vel);
            const float x4 = w   + K41 * (Y1 - C.og1 * w);

            float* ox = &sxo[tid * 5];
            ox[0] = px; ox[1] = py; ox[2] = ang; ox[3] = x3; ox[4] = x4;

            float* op = &cur[tid * 25];   // same-thread overwrite: no barrier needed
            op[0]  = P00; op[1]  = P01; op[2]  = P02; op[3]  = 0.f; op[4]  = 0.f;
            op[5]  = P01; op[6]  = P11; op[7]  = P12; op[8]  = 0.f; op[9]  = 0.f;
            op[10] = P02; op[11] = P12; op[12] = P22; op[13] = 0.f; op[14] = 0.f;
            op[15] = 0.f; op[16] = 0.f; op[17] = 0.f; op[18] = P33; op[19] = 0.f;
            op[20] = 0.f; op[21] = 0.f; op[22] = 0.f; op[23] = 0.f; op[24] = P44;

            sK30[tid] = K30;
            sK41[tid] = K41;
        }
        __syncthreads();   // outputs staged; stage-out reads cross-thread

        // ---- P_new: straight f4 copy ----
        {
            float4* o = (float4*)(outP + (size_t)base * 25);
            const float4* sv = (const float4*)cur;
            const int nf4 = (nv * 25) >> 2;
            #pragma unroll
            for (int k = 0; k < 7; k++) {
                int v = tid + k * BA;
                if (v < nf4) o[v] = sv[v];
            }
            for (int e = nf4 * 4 + tid; e < nv * 25; e += BA)
                outP[(size_t)base * 25 + e] = cur[e];
        }
        // ---- x_new ----
        {
            float4* o = (float4*)(outX + (size_t)base * 5);
            const float4* sv = (const float4*)sxo;
            const int nf4 = (nv * 5) >> 2;
            #pragma unroll
            for (int k = 0; k < 2; k++) {
                int v = tid + k * BA;
                if (v < nf4) o[v] = sv[v];
            }
            for (int e = nf4 * 4 + tid; e < nv * 5; e += BA)
                outX[(size_t)base * 5 + e] = sxo[e];
        }
        // ---- K: synthesized (elems 10n+6 = K30[n], 10n+9 = K41[n]) ----
        {
            float4* o = (float4*)(outK + (size_t)base * 10);
            const int nf4 = (nv * 10) >> 2;
            int m5 = tid % 5;
            #pragma unroll
            for (int k = 0; k < 3; k++) {
                int v = tid + k * BA;
                if (v < nf4) {
                    float4 q = make_float4(0.f, 0.f, 0.f, 0.f);
                    int u = v / 5;
                    if (m5 == 1)      q.z = sK30[2 * u];
                    else if (m5 == 2) q.y = sK41[2 * u];
                    else if (m5 == 4) { q.x = sK30[2 * u + 1]; q.w = sK41[2 * u + 1]; }
                    o[v] = q;
                }
                m5 += 3; if (m5 >= 5) m5 -= 5;
            }
            for (int e = nf4 * 4 + tid; e < nv * 10; e += BA) {
                int n = e / 10, j = e % 10;
                float vv = (j == 6) ? sK30[n] : (j == 9) ? sK41[n] : 0.f;
                outK[(size_t)base * 10 + e] = vv;
            }
        }

        // rotate pipelined scalars
        x0 = nx0; x1 = nx1; x2 = nx2;
        ain0 = na0; ain1 = na1;
        Y0 = nY0; Y1 = nY1;
        // no trailing barrier: next iteration's wait+syncthreads provides ordering
    }
}

extern "C" void kernel_launch(void* const* d_in, const int* in_sizes, int n_in,
                              void* d_out, int out_size) {
    const float* x    = (const float*)d_in[0];
    const float* P    = (const float*)d_in[1];
    const float* a    = (const float*)d_in[2];
    const float* Y    = (const float*)d_in[3];
    const float* n1   = (const float*)d_in[4];
    const float* n2s  = (const float*)d_in[5];
    const float* n2k  = (const float*)d_in[6];
    const float* gns  = (const float*)d_in[7];
    const float* og   = (const float*)d_in[8];
    float* out = (float*)d_out;

    const int N = in_sizes[0] / 5;
    const int totalTiles = (N + BA - 1) / BA;
    int blocks = 148 * 7;                 // persistent: 7 blocks/SM x 148 SMs
    if (blocks > totalTiles) blocks = totalTiles;
    ekf_kernel<<<blocks, BA>>>(x, P, a, Y, n1, n2s, n2k, gns, og, out, N, totalTiles);
}